// round 6
// baseline (speedup 1.0000x reference)
#include <cuda_runtime.h>
#include <cuda_bf16.h>
#include <math.h>

#define L_SEQ   2048
#define BATCH   64
#define EMB     256
#define HID     128
#define G4      512
#define NUTT    128
#define SEP_TOK 50256
#define MTOT    (NUTT * BATCH)   // 8192

typedef unsigned long long u64;

// ---------------- f32x2 helpers (Blackwell packed fp32) ----------------
__device__ __forceinline__ u64 pack2(float lo, float hi) {
    u64 r; asm("mov.b64 %0, {%1, %2};" : "=l"(r) : "f"(lo), "f"(hi)); return r;
}
__device__ __forceinline__ u64 fma2(u64 a, u64 b, u64 c) {
    u64 d; asm("fma.rn.f32x2 %0, %1, %2, %3;" : "=l"(d) : "l"(a), "l"(b), "l"(c)); return d;
}
__device__ __forceinline__ float2 unpack2(u64 v) {
    float2 f; asm("mov.b64 {%0, %1}, %2;" : "=f"(f.x), "=f"(f.y) : "l"(v)); return f;
}

// ---------------- device scratch ----------------
__device__ int   g_seg[L_SEQ * BATCH];
__device__ int   g_ustart[(NUTT + 1) * BATCH];
__device__ float g_u[MTOT * EMB];
__device__ float g_xp[2ull * MTOT * G4];
__device__ float g_h[2ull * MTOT * HID];
__device__ int   g_umask[MTOT];

__device__ __forceinline__ float sig_fast(float x) {
    return __fdividef(1.0f, 1.0f + __expf(-x));
}
__device__ __forceinline__ float tanh_fast(float x) {
    float t = __expf(2.0f * x);
    return 1.0f - __fdividef(2.0f, t + 1.0f);
}

// ---------------- K1: segment ids + utterance starts ----------------
__global__ void k1_seg(const int* __restrict__ x) {
    int b = blockIdx.x, tid = threadIdx.x;
    __shared__ int cnt[256];
    for (int i = tid; i <= NUTT; i += 256) g_ustart[i * BATCH + b] = L_SEQ;
    int base = tid * 8;
    int loc[8]; int c = 0;
    #pragma unroll
    for (int k = 0; k < 8; k++) {
        loc[k] = (x[(base + k) * BATCH + b] == SEP_TOK) ? 1 : 0;
        c += loc[k];
    }
    cnt[tid] = c;
    __syncthreads();
    for (int off = 1; off < 256; off <<= 1) {
        int v = (tid >= off) ? cnt[tid - off] : 0;
        __syncthreads();
        cnt[tid] += v;
        __syncthreads();
    }
    int run = (tid > 0) ? cnt[tid - 1] : 0;
    #pragma unroll
    for (int k = 0; k < 8; k++) {
        int t = base + k;
        g_seg[t * BATCH + b] = run;
        if (loc[k]) {
            if (run + 1 <= NUTT) g_ustart[(run + 1) * BATCH + b] = t + 1;
            run++;
        }
    }
    if (tid == 0) g_ustart[b] = 0;
}

// ---------------- K2: ragged mean-pool ----------------
__global__ void k2_pool(const int* __restrict__ x, const float* __restrict__ emb) {
    int uu = blockIdx.x, b = blockIdx.y;
    __shared__ int rows[L_SEQ];
    __shared__ int se[2];
    if (threadIdx.x < 2)
        se[threadIdx.x] = g_ustart[(uu + threadIdx.x) * BATCH + b];
    __syncthreads();
    int s = se[0], e = se[1];
    for (int t = s + threadIdx.x; t < e; t += 256) rows[t - s] = x[t * BATCH + b];
    __syncthreads();
    int n = e - s;
    float sum = 0.f;
    for (int i = 0; i < n; i++)
        sum += emb[(size_t)rows[i] * EMB + threadIdx.x];
    g_u[((size_t)uu * BATCH + b) * EMB + threadIdx.x] = (n > 0) ? sum / (float)n : 0.f;
}

// ---------------- K3: xp = U @ Wcat^T + biases (f32x2, smem-native packing) ----------------
#define BM 128
#define BN 128
#define BKK 16
#define NKT (EMB / BKK)
__global__ void __launch_bounds__(256) k3_gemm(
    const float* __restrict__ wihf, const float* __restrict__ wihb,
    const float* __restrict__ bihf, const float* __restrict__ bhhf,
    const float* __restrict__ bihb, const float* __restrict__ bhhb) {
    __shared__ u64   As2[2][BKK][BM];       // a duplicated pairs: 32 KB
    __shared__ float Bs[2][BKK][BN + 4];    // 16.9 KB
    int m0 = blockIdx.x * BM, n0 = blockIdx.y * BN;
    int tid = threadIdx.x;
    int tx = tid & 15, ty = tid >> 4;
    u64 acc2[8][4];
    #pragma unroll
    for (int i = 0; i < 8; i++)
        #pragma unroll
        for (int j = 0; j < 4; j++) acc2[i][j] = 0ull;

    int t2a = tid * 2, t2b = tid * 2 + 1;
    int ra = t2a >> 2, ca = (t2a & 3) * 4;
    int rb = t2b >> 2, cb = (t2b & 3) * 4;
    int na = n0 + ra, nb = n0 + rb;
    const float* bpa = (na < G4) ? &wihf[(size_t)na * EMB] : &wihb[(size_t)(na - G4) * EMB];
    const float* bpb = (nb < G4) ? &wihf[(size_t)nb * EMB] : &wihb[(size_t)(nb - G4) * EMB];
    const float* apa = &g_u[(size_t)(m0 + ra) * EMB];
    const float* apb = &g_u[(size_t)(m0 + rb) * EMB];

    float4 av0, av1, bv0, bv1;
    av0 = *(const float4*)&apa[ca];
    av1 = *(const float4*)&apb[cb];
    bv0 = *(const float4*)&bpa[ca];
    bv1 = *(const float4*)&bpb[cb];
    {
        As2[0][ca + 0][ra] = pack2(av0.x, av0.x); As2[0][ca + 1][ra] = pack2(av0.y, av0.y);
        As2[0][ca + 2][ra] = pack2(av0.z, av0.z); As2[0][ca + 3][ra] = pack2(av0.w, av0.w);
        As2[0][cb + 0][rb] = pack2(av1.x, av1.x); As2[0][cb + 1][rb] = pack2(av1.y, av1.y);
        As2[0][cb + 2][rb] = pack2(av1.z, av1.z); As2[0][cb + 3][rb] = pack2(av1.w, av1.w);
        Bs[0][ca + 0][ra] = bv0.x; Bs[0][ca + 1][ra] = bv0.y;
        Bs[0][ca + 2][ra] = bv0.z; Bs[0][ca + 3][ra] = bv0.w;
        Bs[0][cb + 0][rb] = bv1.x; Bs[0][cb + 1][rb] = bv1.y;
        Bs[0][cb + 2][rb] = bv1.z; Bs[0][cb + 3][rb] = bv1.w;
    }
    __syncthreads();

    #pragma unroll 1
    for (int kt = 0; kt < NKT; kt++) {
        int cur = kt & 1;
        if (kt + 1 < NKT) {
            int k0 = (kt + 1) * BKK;
            av0 = *(const float4*)&apa[k0 + ca];
            av1 = *(const float4*)&apb[k0 + cb];
            bv0 = *(const float4*)&bpa[k0 + ca];
            bv1 = *(const float4*)&bpb[k0 + cb];
        }
        #pragma unroll
        for (int kk = 0; kk < BKK; kk++) {
            ulonglong2 q0 = *(const ulonglong2*)&Bs[cur][kk][tx * 8];
            ulonglong2 q1 = *(const ulonglong2*)&Bs[cur][kk][tx * 8 + 4];
            u64 b2[4] = {q0.x, q0.y, q1.x, q1.y};
            #pragma unroll
            for (int i = 0; i < 8; i++) {
                u64 a2 = As2[cur][kk][ty * 8 + i];
                #pragma unroll
                for (int jp = 0; jp < 4; jp++)
                    acc2[i][jp] = fma2(a2, b2[jp], acc2[i][jp]);
            }
        }
        if (kt + 1 < NKT) {
            int nxt = 1 - cur;
            As2[nxt][ca + 0][ra] = pack2(av0.x, av0.x); As2[nxt][ca + 1][ra] = pack2(av0.y, av0.y);
            As2[nxt][ca + 2][ra] = pack2(av0.z, av0.z); As2[nxt][ca + 3][ra] = pack2(av0.w, av0.w);
            As2[nxt][cb + 0][rb] = pack2(av1.x, av1.x); As2[nxt][cb + 1][rb] = pack2(av1.y, av1.y);
            As2[nxt][cb + 2][rb] = pack2(av1.z, av1.z); As2[nxt][cb + 3][rb] = pack2(av1.w, av1.w);
            Bs[nxt][ca + 0][ra] = bv0.x; Bs[nxt][ca + 1][ra] = bv0.y;
            Bs[nxt][ca + 2][ra] = bv0.z; Bs[nxt][ca + 3][ra] = bv0.w;
            Bs[nxt][cb + 0][rb] = bv1.x; Bs[nxt][cb + 1][rb] = bv1.y;
            Bs[nxt][cb + 2][rb] = bv1.z; Bs[nxt][cb + 3][rb] = bv1.w;
            __syncthreads();
        }
    }
    #pragma unroll
    for (int i = 0; i < 8; i++) {
        int m = m0 + ty * 8 + i;
        #pragma unroll
        for (int jp = 0; jp < 4; jp++) {
            float2 v = unpack2(acc2[i][jp]);
            #pragma unroll
            for (int h = 0; h < 2; h++) {
                int n   = n0 + tx * 8 + 2 * jp + h;
                int dir = n >> 9;
                int gi  = n & (G4 - 1);
                float bias = dir ? (bihb[gi] + bhhb[gi]) : (bihf[gi] + bhhf[gi]);
                g_xp[((size_t)dir * MTOT + m) * G4 + gi] = (h ? v.y : v.x) + bias;
            }
        }
    }
}

// ---------------- K4: persistent BiLSTM (f32x2, no packs, spill-free target) ----------------
#define WS2_S  257                       // stride in u64
#define WS2_U64 (32 * WS2_S)             // 8224 u64 = 65792 B
#define K4_SMEM_BYTES (WS2_U64 * 8 + (512 + 128) * 4)

__global__ void __launch_bounds__(256, 1) k4_lstm(
    const float* __restrict__ whhf, const float* __restrict__ whhb) {
    extern __shared__ u64 smu[];
    u64*   ws2 = smu;
    float* gsm = (float*)(smu + WS2_U64);
    float* hsm = gsm + 512;              // 16B-aligned

    int bi = blockIdx.x;
    int dir = bi >> 6, b = bi & 63;
    const float* whh = dir ? whhb : whhf;
    int tid = threadIdx.x;

    // smem: j-pairs 32..63 (j=64..127) of rows 0..255 (i/f gates), transposed
    #pragma unroll
    for (int jp = 0; jp < 32; jp++)
        ws2[jp * WS2_S + tid] = *(const u64*)&whh[(size_t)tid * HID + 64 + 2 * jp];
    // registers: full g/o row (64 u64) + first half of i/f row (32 u64)
    u64 wgop[64];
    {
        const u64* wr = (const u64*)(whh + (size_t)(256 + tid) * HID);
        #pragma unroll
        for (int q = 0; q < 64; q++) wgop[q] = wr[q];
    }
    u64 wifp[32];
    {
        const u64* wr = (const u64*)(whh + (size_t)tid * HID);
        #pragma unroll
        for (int q = 0; q < 32; q++) wifp[q] = wr[q];
    }
    if (tid < HID) hsm[tid] = 0.f;
    float c = 0.f;
    __syncthreads();

    int t0 = dir ? (NUTT - 1) : 0;
    size_t base0 = ((size_t)dir * MTOT + (size_t)t0 * BATCH + b) * G4;
    float xpA = g_xp[base0 + tid];
    float xpB = g_xp[base0 + 256 + tid];
    float xpA_n = 0.f, xpB_n = 0.f;

    #pragma unroll 1
    for (int s = 0; s < NUTT; s++) {
        int t = dir ? (NUTT - 1 - s) : s;
        if (s + 1 < NUTT) {
            int tn = dir ? (NUTT - 2 - s) : (s + 1);
            size_t bn = ((size_t)dir * MTOT + (size_t)tn * BATCH + b) * G4;
            xpA_n = g_xp[bn + tid];
            xpB_n = g_xp[bn + 256 + tid];
        }

        u64 aA0 = 0ull, aA1 = 0ull, aB0 = 0ull, aB1 = 0ull;
        // j = 0..63 : i/f weights from regs; h pairs loaded straight from smem
        #pragma unroll
        for (int u = 0; u < 16; u++) {
            ulonglong2 h2 = *(const ulonglong2*)&hsm[4 * u];
            aA0 = fma2(wifp[2 * u],     h2.x, aA0);
            aA1 = fma2(wifp[2 * u + 1], h2.y, aA1);
            aB0 = fma2(wgop[2 * u],     h2.x, aB0);
            aB1 = fma2(wgop[2 * u + 1], h2.y, aB1);
        }
        // j = 64..127 : i/f weights from smem
        #pragma unroll
        for (int u = 0; u < 16; u++) {
            ulonglong2 h2 = *(const ulonglong2*)&hsm[64 + 4 * u];
            aA0 = fma2(ws2[(2 * u)     * WS2_S + tid], h2.x, aA0);
            aA1 = fma2(ws2[(2 * u + 1) * WS2_S + tid], h2.y, aA1);
            aB0 = fma2(wgop[32 + 2 * u],     h2.x, aB0);
            aB1 = fma2(wgop[32 + 2 * u + 1], h2.y, aB1);
        }
        float2 vA0 = unpack2(aA0), vA1 = unpack2(aA1);
        float2 vB0 = unpack2(aB0), vB1 = unpack2(aB1);
        gsm[tid]       = (vA0.x + vA0.y) + (vA1.x + vA1.y) + xpA;
        gsm[256 + tid] = (vB0.x + vB0.y) + (vB1.x + vB1.y) + xpB;
        __syncthreads();
        if (tid < HID) {
            float gi = gsm[tid], gf = gsm[HID + tid];
            float gg = gsm[256 + tid], go = gsm[384 + tid];
            c = sig_fast(gf) * c + sig_fast(gi) * tanh_fast(gg);
            float h = sig_fast(go) * tanh_fast(c);
            hsm[tid] = h;
            g_h[(((size_t)dir * NUTT + t) * BATCH + b) * HID + tid] = h;
        }
        xpA = xpA_n;
        xpB = xpB_n;
        __syncthreads();
    }
}

// ---------------- K5: head (warp per (t,b)) ----------------
__global__ void k5_head(const float* __restrict__ wout, const float* __restrict__ bout,
                        float* __restrict__ out) {
    int w = threadIdx.x >> 5, lane = threadIdx.x & 31;
    int idx = blockIdx.x * 8 + w;
    if (idx >= MTOT) return;
    int t = idx >> 6, b = idx & 63;
    const float* hf = &g_h[(((size_t)0 * NUTT + t) * BATCH + b) * HID];
    const float* hb = &g_h[(((size_t)1 * NUTT + t) * BATCH + b) * HID];
    float l0 = 0.f, l1 = 0.f;
    #pragma unroll
    for (int q = 0; q < 4; q++) {
        int e = q * 32 + lane;
        float vf = hf[e], vb = hb[e];
        l0 += vf * wout[e] + vb * wout[HID + e];
        l1 += vf * wout[EMB + e] + vb * wout[EMB + HID + e];
    }
    #pragma unroll
    for (int off = 16; off > 0; off >>= 1) {
        l0 += __shfl_xor_sync(0xFFFFFFFFu, l0, off);
        l1 += __shfl_xor_sync(0xFFFFFFFFu, l1, off);
    }
    if (lane == 0) {
        l0 += bout[0]; l1 += bout[1];
        float m  = fmaxf(l0, l1);
        float e0 = expf(l0 - m), e1 = expf(l1 - m);
        float s  = e0 + e1;
        float p0 = e0 / s, p1 = e1 / s;
        int am = (l1 > l0) ? 1 : 0;
        out[idx * 2 + 0]         = l0;
        out[idx * 2 + 1]         = l1;
        out[16384 + idx * 2 + 0] = p0;
        out[16384 + idx * 2 + 1] = p1;
        out[32768 + idx]         = am ? p1 : p0;
        out[40960 + idx]         = (float)am;
        g_umask[idx]             = am;
    }
}

// ---------------- K6: expand mask to tokens ----------------
__global__ void k6_mask(const int* __restrict__ x, float* __restrict__ out) {
    int i = blockIdx.x * blockDim.x + threadIdx.x;
    if (i >= L_SEQ * BATCH) return;
    int b   = i & 63;
    int seg = g_seg[i];
    int m   = g_umask[seg * BATCH + b];
    out[49152 + i] = m ? (float)x[i] : 0.0f;
}

extern "C" void kernel_launch(void* const* d_in, const int* in_sizes, int n_in,
                              void* d_out, int out_size) {
    const int*   x    = (const int*)d_in[0];
    const float* emb  = (const float*)d_in[1];
    const float* wihf = (const float*)d_in[2];
    const float* whhf = (const float*)d_in[3];
    const float* bihf = (const float*)d_in[4];
    const float* bhhf = (const float*)d_in[5];
    const float* wihb = (const float*)d_in[6];
    const float* whhb = (const float*)d_in[7];
    const float* bihb = (const float*)d_in[8];
    const float* bhhb = (const float*)d_in[9];
    const float* wout = (const float*)d_in[10];
    const float* bout = (const float*)d_in[11];
    float* out = (float*)d_out;

    cudaFuncSetAttribute(k4_lstm, cudaFuncAttributeMaxDynamicSharedMemorySize, K4_SMEM_BYTES);

    k1_seg <<<BATCH, 256>>>(x);
    k2_pool<<<dim3(NUTT, BATCH), 256>>>(x, emb);
    k3_gemm<<<dim3(MTOT / BM, (2 * G4) / BN), 256>>>(wihf, wihb, bihf, bhhf, bihb, bhhb);
    k4_lstm<<<2 * BATCH, 256, K4_SMEM_BYTES>>>(whhf, whhb);
    k5_head<<<MTOT / 8, 256>>>(wout, bout, out);
    k6_mask<<<(L_SEQ * BATCH) / 256, 256>>>(x, out);
}

// round 8
// speedup vs baseline: 1.5281x; 1.5281x over previous
#include <cuda_runtime.h>
#include <cuda_bf16.h>
#include <math.h>
#include <cstdint>

#define L_SEQ   2048
#define BATCH   64
#define EMB     256
#define HID     128
#define G4      512
#define NUTT    128
#define SEP_TOK 50256
#define MTOT    (NUTT * BATCH)   // 8192

typedef unsigned long long u64;

// ---------------- f32x2 helpers ----------------
__device__ __forceinline__ u64 fma2(u64 a, u64 b, u64 c) {
    u64 d; asm("fma.rn.f32x2 %0, %1, %2, %3;" : "=l"(d) : "l"(a), "l"(b), "l"(c)); return d;
}
__device__ __forceinline__ float2 unpack2(u64 v) {
    float2 f; asm("mov.b64 {%0, %1}, %2;" : "=f"(f.x), "=f"(f.y) : "l"(v)); return f;
}

__device__ __forceinline__ uint32_t smem_to_u32(const void* p) {
    uint32_t a;
    asm("{ .reg .u64 t; cvta.to.shared.u64 t, %1; cvt.u32.u64 %0, t; }" : "=r"(a) : "l"(p));
    return a;
}

// ---------------- mma.sync / ldmatrix / cp.async (sm_80-compatible PTX) ----------------
#define CP_ASYNC16(smem, gptr) \
    asm volatile("cp.async.ca.shared.global [%0], [%1], 16;" :: "r"(smem), "l"(gptr))
#define CP_COMMIT() asm volatile("cp.async.commit_group;" ::: "memory")
#define CP_WAIT1()  asm volatile("cp.async.wait_group 1;" ::: "memory")
#define CP_WAIT0()  asm volatile("cp.async.wait_group 0;" ::: "memory")

#define LDMATRIX_X4(r0, r1, r2, r3, addr) \
    asm volatile("ldmatrix.sync.aligned.m8n8.x4.shared.b16 {%0,%1,%2,%3}, [%4];" \
                 : "=r"(r0), "=r"(r1), "=r"(r2), "=r"(r3) : "r"(addr))

__device__ __forceinline__ void mma16816(float* d, const uint32_t* a, uint32_t b0, uint32_t b1) {
    asm volatile(
        "mma.sync.aligned.m16n8k16.row.col.f32.bf16.bf16.f32 "
        "{%0,%1,%2,%3}, {%4,%5,%6,%7}, {%8,%9}, {%0,%1,%2,%3};"
        : "+f"(d[0]), "+f"(d[1]), "+f"(d[2]), "+f"(d[3])
        : "r"(a[0]), "r"(a[1]), "r"(a[2]), "r"(a[3]), "r"(b0), "r"(b1));
}

// ---------------- device scratch ----------------
__device__ int            g_seg[L_SEQ * BATCH];
__device__ int            g_ustart[(NUTT + 1) * BATCH];
__device__ __nv_bfloat16  g_uhi[MTOT * EMB];
__device__ __nv_bfloat16  g_ulo[MTOT * EMB];
__device__ __nv_bfloat16  g_whi[2 * G4 * EMB];
__device__ __nv_bfloat16  g_wlo[2 * G4 * EMB];
__device__ float          g_xp[2ull * MTOT * G4];
__device__ float          g_h[2ull * MTOT * HID];
__device__ int            g_umask[MTOT];

__device__ __forceinline__ float sig_fast(float x) {
    return __fdividef(1.0f, 1.0f + __expf(-x));
}
__device__ __forceinline__ float tanh_fast(float x) {
    float t = __expf(2.0f * x);
    return 1.0f - __fdividef(2.0f, t + 1.0f);
}

// ---------------- K1: segment ids + utterance starts ----------------
__global__ void k1_seg(const int* __restrict__ x) {
    int b = blockIdx.x, tid = threadIdx.x;
    __shared__ int cnt[256];
    for (int i = tid; i <= NUTT; i += 256) g_ustart[i * BATCH + b] = L_SEQ;
    int base = tid * 8;
    int loc[8]; int c = 0;
    #pragma unroll
    for (int k = 0; k < 8; k++) {
        loc[k] = (x[(base + k) * BATCH + b] == SEP_TOK) ? 1 : 0;
        c += loc[k];
    }
    cnt[tid] = c;
    __syncthreads();
    for (int off = 1; off < 256; off <<= 1) {
        int v = (tid >= off) ? cnt[tid - off] : 0;
        __syncthreads();
        cnt[tid] += v;
        __syncthreads();
    }
    int run = (tid > 0) ? cnt[tid - 1] : 0;
    #pragma unroll
    for (int k = 0; k < 8; k++) {
        int t = base + k;
        g_seg[t * BATCH + b] = run;
        if (loc[k]) {
            if (run + 1 <= NUTT) g_ustart[(run + 1) * BATCH + b] = t + 1;
            run++;
        }
    }
    if (tid == 0) g_ustart[b] = 0;
}

// ---------------- K2: ragged mean-pool -> bf16 hi/lo ----------------
__global__ void k2_pool(const int* __restrict__ x, const float* __restrict__ emb) {
    int uu = blockIdx.x, b = blockIdx.y;
    __shared__ int rows[L_SEQ];
    __shared__ int se[2];
    if (threadIdx.x < 2)
        se[threadIdx.x] = g_ustart[(uu + threadIdx.x) * BATCH + b];
    __syncthreads();
    int s = se[0], e = se[1];
    for (int t = s + threadIdx.x; t < e; t += 256) rows[t - s] = x[t * BATCH + b];
    __syncthreads();
    int n = e - s;
    float sum = 0.f;
    for (int i = 0; i < n; i++)
        sum += emb[(size_t)rows[i] * EMB + threadIdx.x];
    float val = (n > 0) ? sum / (float)n : 0.f;
    size_t idx = ((size_t)uu * BATCH + b) * EMB + threadIdx.x;
    __nv_bfloat16 hi = __float2bfloat16(val);
    g_uhi[idx] = hi;
    g_ulo[idx] = __float2bfloat16(val - __bfloat162float(hi));
}

// ---------------- K3w: weight hi/lo conversion ----------------
__global__ void k3w_conv(const float* __restrict__ wihf, const float* __restrict__ wihb) {
    int n = blockIdx.x;
    int col = threadIdx.x;
    float w = (n < G4) ? wihf[(size_t)n * EMB + col] : wihb[(size_t)(n - G4) * EMB + col];
    __nv_bfloat16 hi = __float2bfloat16(w);
    size_t idx = (size_t)n * EMB + col;
    g_whi[idx] = hi;
    g_wlo[idx] = __float2bfloat16(w - __bfloat162float(hi));
}

// ---------------- K3b: HMMA GEMM xp = U @ Wcat^T + biases ----------------
// One virtual GEMM over K'=768 = 3 splits (AhBh, AhBl, AlBh) x K=256.
// Block M128 x N64 x K64, cp.async double-buffered, 8 warps (4M x 2N).
#define K3_BM 128
#define K3_BN 64
#define K3_BK 64
#define K3_STR 72                            // bf16 elems per smem row (144 B, LDSM conflict-free)
#define K3_A_BYTES (K3_BM * K3_STR * 2)      // 18432
#define K3_B_BYTES (K3_BN * K3_STR * 2)      // 9216
#define K3_SMEM (2 * (K3_A_BYTES + K3_B_BYTES))  // 55296

__global__ void __launch_bounds__(256) k3b_gemm(
    const float* __restrict__ bihf, const float* __restrict__ bhhf,
    const float* __restrict__ bihb, const float* __restrict__ bhhb) {
    extern __shared__ char dsm[];
    __shared__ float bias_sm[K3_BN];
    uint32_t smb = smem_to_u32(dsm);
    const uint32_t aoff[2] = {0u, (uint32_t)K3_A_BYTES};
    const uint32_t boff[2] = {(uint32_t)(2 * K3_A_BYTES), (uint32_t)(2 * K3_A_BYTES + K3_B_BYTES)};

    int tid = threadIdx.x;
    int wid = tid >> 5, lane = tid & 31;
    int warp_m = wid & 3, warp_n = wid >> 2;
    int m0 = blockIdx.x * K3_BM;
    int n0 = blockIdx.y * K3_BN;
    int dir = n0 >> 9;
    int gi0 = n0 & (G4 - 1);

    if (tid < K3_BN) {
        int gi = gi0 + tid;
        bias_sm[tid] = dir ? (bihb[gi] + bhhb[gi]) : (bihf[gi] + bhhf[gi]);
    }

    float acc[2][4][4];
    #pragma unroll
    for (int a = 0; a < 2; a++)
        #pragma unroll
        for (int b = 0; b < 4; b++)
            #pragma unroll
            for (int cc = 0; cc < 4; cc++) acc[a][b][cc] = 0.f;

    int arow = tid >> 3, ac8 = tid & 7;      // A chunk coords (row strides +32)
    int brow = tid >> 3, bc8 = tid & 7;      // B chunk coords (row strides +32)

    // ---- stage loader: split s = ks/4, k0 = (ks%4)*64 ----
    #define K3_LOAD_STAGE(ks, buf) do {                                              \
        int _s = (ks) >> 2;                                                          \
        int _k0 = ((ks) & 3) * K3_BK;                                                \
        const __nv_bfloat16* _As = (_s < 2) ? g_uhi : g_ulo;                         \
        const __nv_bfloat16* _Bs = (_s == 1) ? g_wlo : g_whi;                        \
        _Pragma("unroll")                                                            \
        for (int _i = 0; _i < 4; _i++) {                                             \
            int _r = arow + _i * 32;                                                 \
            const void* _g = _As + (size_t)(m0 + _r) * EMB + _k0 + ac8 * 8;          \
            uint32_t _d = smb + aoff[buf] + (uint32_t)(_r * K3_STR + ac8 * 8) * 2;   \
            CP_ASYNC16(_d, _g);                                                      \
        }                                                                            \
        _Pragma("unroll")                                                            \
        for (int _i = 0; _i < 2; _i++) {                                             \
            int _r = brow + _i * 32;                                                 \
            const void* _g = _Bs + (size_t)(n0 + _r) * EMB + _k0 + bc8 * 8;          \
            uint32_t _d = smb + boff[buf] + (uint32_t)(_r * K3_STR + bc8 * 8) * 2;   \
            CP_ASYNC16(_d, _g);                                                      \
        }                                                                            \
        CP_COMMIT();                                                                 \
    } while (0)

    K3_LOAD_STAGE(0, 0);

    #pragma unroll 1
    for (int ks = 0; ks < 12; ks++) {
        if (ks + 1 < 12) {
            K3_LOAD_STAGE(ks + 1, (ks + 1) & 1);
            CP_WAIT1();
        } else {
            CP_WAIT0();
        }
        __syncthreads();
        int buf = ks & 1;
        uint32_t Ab = smb + aoff[buf];
        uint32_t Bb = smb + boff[buf];
        #pragma unroll
        for (int kk = 0; kk < 4; kk++) {
            uint32_t af[2][4], bf[2][4];
            #pragma unroll
            for (int mt = 0; mt < 2; mt++) {
                int row = warp_m * 32 + mt * 16 + (lane & 15);
                int col = kk * 16 + (lane >> 4) * 8;
                LDMATRIX_X4(af[mt][0], af[mt][1], af[mt][2], af[mt][3],
                            Ab + (uint32_t)(row * K3_STR + col) * 2);
            }
            #pragma unroll
            for (int nt = 0; nt < 2; nt++) {
                int row = warp_n * 32 + nt * 16 + (lane & 15);
                int col = kk * 16 + (lane >> 4) * 8;
                LDMATRIX_X4(bf[nt][0], bf[nt][1], bf[nt][2], bf[nt][3],
                            Bb + (uint32_t)(row * K3_STR + col) * 2);
            }
            #pragma unroll
            for (int mt = 0; mt < 2; mt++)
                #pragma unroll
                for (int nt = 0; nt < 2; nt++) {
                    mma16816(acc[mt][nt * 2 + 0], af[mt], bf[nt][0], bf[nt][2]);
                    mma16816(acc[mt][nt * 2 + 1], af[mt], bf[nt][1], bf[nt][3]);
                }
        }
        __syncthreads();
    }

    // epilogue: add bias, scatter to g_xp
    int lrow = lane >> 2, lcol = (lane & 3) * 2;
    #pragma unroll
    for (int mt = 0; mt < 2; mt++) {
        int m = m0 + warp_m * 32 + mt * 16 + lrow;
        #pragma unroll
        for (int n8 = 0; n8 < 4; n8++) {
            int nl = warp_n * 32 + n8 * 8 + lcol;
            float b0 = bias_sm[nl], b1 = bias_sm[nl + 1];
            float2 v0 = make_float2(acc[mt][n8][0] + b0, acc[mt][n8][1] + b1);
            float2 v1 = make_float2(acc[mt][n8][2] + b0, acc[mt][n8][3] + b1);
            *(float2*)&g_xp[((size_t)dir * MTOT + m) * G4 + gi0 + nl]     = v0;
            *(float2*)&g_xp[((size_t)dir * MTOT + m + 8) * G4 + gi0 + nl] = v1;
        }
    }
}

// ---------------- K4: persistent BiLSTM (unchanged, known 114.5us) ----------------
#define WS2_S  257
#define WS2_U64 (32 * WS2_S)
#define K4_SMEM_BYTES (WS2_U64 * 8 + (512 + 128) * 4)

__global__ void __launch_bounds__(256, 1) k4_lstm(
    const float* __restrict__ whhf, const float* __restrict__ whhb) {
    extern __shared__ u64 smu[];
    u64*   ws2 = smu;
    float* gsm = (float*)(smu + WS2_U64);
    float* hsm = gsm + 512;

    int bi = blockIdx.x;
    int dir = bi >> 6, b = bi & 63;
    const float* whh = dir ? whhb : whhf;
    int tid = threadIdx.x;

    #pragma unroll
    for (int jp = 0; jp < 32; jp++)
        ws2[jp * WS2_S + tid] = *(const u64*)&whh[(size_t)tid * HID + 64 + 2 * jp];
    u64 wgop[64];
    {
        const u64* wr = (const u64*)(whh + (size_t)(256 + tid) * HID);
        #pragma unroll
        for (int q = 0; q < 64; q++) wgop[q] = wr[q];
    }
    u64 wifp[32];
    {
        const u64* wr = (const u64*)(whh + (size_t)tid * HID);
        #pragma unroll
        for (int q = 0; q < 32; q++) wifp[q] = wr[q];
    }
    if (tid < HID) hsm[tid] = 0.f;
    float c = 0.f;
    __syncthreads();

    int t0 = dir ? (NUTT - 1) : 0;
    size_t base0 = ((size_t)dir * MTOT + (size_t)t0 * BATCH + b) * G4;
    float xpA = g_xp[base0 + tid];
    float xpB = g_xp[base0 + 256 + tid];
    float xpA_n = 0.f, xpB_n = 0.f;

    #pragma unroll 1
    for (int s = 0; s < NUTT; s++) {
        int t = dir ? (NUTT - 1 - s) : s;
        if (s + 1 < NUTT) {
            int tn = dir ? (NUTT - 2 - s) : (s + 1);
            size_t bn = ((size_t)dir * MTOT + (size_t)tn * BATCH + b) * G4;
            xpA_n = g_xp[bn + tid];
            xpB_n = g_xp[bn + 256 + tid];
        }

        u64 aA0 = 0ull, aA1 = 0ull, aB0 = 0ull, aB1 = 0ull;
        #pragma unroll
        for (int u = 0; u < 16; u++) {
            ulonglong2 h2 = *(const ulonglong2*)&hsm[4 * u];
            aA0 = fma2(wifp[2 * u],     h2.x, aA0);
            aA1 = fma2(wifp[2 * u + 1], h2.y, aA1);
            aB0 = fma2(wgop[2 * u],     h2.x, aB0);
            aB1 = fma2(wgop[2 * u + 1], h2.y, aB1);
        }
        #pragma unroll
        for (int u = 0; u < 16; u++) {
            ulonglong2 h2 = *(const ulonglong2*)&hsm[64 + 4 * u];
            aA0 = fma2(ws2[(2 * u)     * WS2_S + tid], h2.x, aA0);
            aA1 = fma2(ws2[(2 * u + 1) * WS2_S + tid], h2.y, aA1);
            aB0 = fma2(wgop[32 + 2 * u],     h2.x, aB0);
            aB1 = fma2(wgop[32 + 2 * u + 1], h2.y, aB1);
        }
        float2 vA0 = unpack2(aA0), vA1 = unpack2(aA1);
        float2 vB0 = unpack2(aB0), vB1 = unpack2(aB1);
        gsm[tid]       = (vA0.x + vA0.y) + (vA1.x + vA1.y) + xpA;
        gsm[256 + tid] = (vB0.x + vB0.y) + (vB1.x + vB1.y) + xpB;
        __syncthreads();
        if (tid < HID) {
            float gi = gsm[tid], gf = gsm[HID + tid];
            float gg = gsm[256 + tid], go = gsm[384 + tid];
            c = sig_fast(gf) * c + sig_fast(gi) * tanh_fast(gg);
            float h = sig_fast(go) * tanh_fast(c);
            hsm[tid] = h;
            g_h[(((size_t)dir * NUTT + t) * BATCH + b) * HID + tid] = h;
        }
        xpA = xpA_n;
        xpB = xpB_n;
        __syncthreads();
    }
}

// ---------------- K5: head (warp per (t,b)) ----------------
__global__ void k5_head(const float* __restrict__ wout, const float* __restrict__ bout,
                        float* __restrict__ out) {
    int w = threadIdx.x >> 5, lane = threadIdx.x & 31;
    int idx = blockIdx.x * 8 + w;
    if (idx >= MTOT) return;
    int t = idx >> 6, b = idx & 63;
    const float* hf = &g_h[(((size_t)0 * NUTT + t) * BATCH + b) * HID];
    const float* hb = &g_h[(((size_t)1 * NUTT + t) * BATCH + b) * HID];
    float l0 = 0.f, l1 = 0.f;
    #pragma unroll
    for (int q = 0; q < 4; q++) {
        int e = q * 32 + lane;
        float vf = hf[e], vb = hb[e];
        l0 += vf * wout[e] + vb * wout[HID + e];
        l1 += vf * wout[EMB + e] + vb * wout[EMB + HID + e];
    }
    #pragma unroll
    for (int off = 16; off > 0; off >>= 1) {
        l0 += __shfl_xor_sync(0xFFFFFFFFu, l0, off);
        l1 += __shfl_xor_sync(0xFFFFFFFFu, l1, off);
    }
    if (lane == 0) {
        l0 += bout[0]; l1 += bout[1];
        float m  = fmaxf(l0, l1);
        float e0 = expf(l0 - m), e1 = expf(l1 - m);
        float s  = e0 + e1;
        float p0 = e0 / s, p1 = e1 / s;
        int am = (l1 > l0) ? 1 : 0;
        out[idx * 2 + 0]         = l0;
        out[idx * 2 + 1]         = l1;
        out[16384 + idx * 2 + 0] = p0;
        out[16384 + idx * 2 + 1] = p1;
        out[32768 + idx]         = am ? p1 : p0;
        out[40960 + idx]         = (float)am;
        g_umask[idx]             = am;
    }
}

// ---------------- K6: expand mask to tokens ----------------
__global__ void k6_mask(const int* __restrict__ x, float* __restrict__ out) {
    int i = blockIdx.x * blockDim.x + threadIdx.x;
    if (i >= L_SEQ * BATCH) return;
    int b   = i & 63;
    int seg = g_seg[i];
    int m   = g_umask[seg * BATCH + b];
    out[49152 + i] = m ? (float)x[i] : 0.0f;
}

extern "C" void kernel_launch(void* const* d_in, const int* in_sizes, int n_in,
                              void* d_out, int out_size) {
    const int*   x    = (const int*)d_in[0];
    const float* emb  = (const float*)d_in[1];
    const float* wihf = (const float*)d_in[2];
    const float* whhf = (const float*)d_in[3];
    const float* bihf = (const float*)d_in[4];
    const float* bhhf = (const float*)d_in[5];
    const float* wihb = (const float*)d_in[6];
    const float* whhb = (const float*)d_in[7];
    const float* bihb = (const float*)d_in[8];
    const float* bhhb = (const float*)d_in[9];
    const float* wout = (const float*)d_in[10];
    const float* bout = (const float*)d_in[11];
    float* out = (float*)d_out;

    cudaFuncSetAttribute(k4_lstm, cudaFuncAttributeMaxDynamicSharedMemorySize, K4_SMEM_BYTES);
    cudaFuncSetAttribute(k3b_gemm, cudaFuncAttributeMaxDynamicSharedMemorySize, K3_SMEM);

    k3w_conv<<<2 * G4, EMB>>>(wihf, wihb);
    k1_seg <<<BATCH, 256>>>(x);
    k2_pool<<<dim3(NUTT, BATCH), 256>>>(x, emb);
    k3b_gemm<<<dim3(MTOT / K3_BM, (2 * G4) / K3_BN), 256, K3_SMEM>>>(bihf, bhhf, bihb, bhhb);
    k4_lstm<<<2 * BATCH, 256, K4_SMEM_BYTES>>>(whhf, whhb);
    k5_head<<<MTOT / 8, 256>>>(wout, bout, out);
    k6_mask<<<(L_SEQ * BATCH) / 256, 256>>>(x, out);
}

// round 9
// speedup vs baseline: 1.5675x; 1.0258x over previous
#include <cuda_runtime.h>
#include <cuda_bf16.h>
#include <math.h>
#include <cstdint>

#define L_SEQ   2048
#define BATCH   64
#define EMB     256
#define HID     128
#define G4      512
#define NUTT    128
#define SEP_TOK 50256
#define MTOT    (NUTT * BATCH)   // 8192

typedef unsigned long long u64;

// ---------------- f32x2 helpers ----------------
__device__ __forceinline__ u64 fma2(u64 a, u64 b, u64 c) {
    u64 d; asm("fma.rn.f32x2 %0, %1, %2, %3;" : "=l"(d) : "l"(a), "l"(b), "l"(c)); return d;
}
__device__ __forceinline__ float2 unpack2(u64 v) {
    float2 f; asm("mov.b64 {%0, %1}, %2;" : "=f"(f.x), "=f"(f.y) : "l"(v)); return f;
}

__device__ __forceinline__ uint32_t smem_to_u32(const void* p) {
    uint32_t a;
    asm("{ .reg .u64 t; cvta.to.shared.u64 t, %1; cvt.u32.u64 %0, t; }" : "=r"(a) : "l"(p));
    return a;
}

// ---------------- mma.sync / ldmatrix / cp.async ----------------
#define CP_ASYNC16(smem, gptr) \
    asm volatile("cp.async.ca.shared.global [%0], [%1], 16;" :: "r"(smem), "l"(gptr))
#define CP_COMMIT() asm volatile("cp.async.commit_group;" ::: "memory")
#define CP_WAIT1()  asm volatile("cp.async.wait_group 1;" ::: "memory")
#define CP_WAIT0()  asm volatile("cp.async.wait_group 0;" ::: "memory")

#define LDMATRIX_X4(r0, r1, r2, r3, addr) \
    asm volatile("ldmatrix.sync.aligned.m8n8.x4.shared.b16 {%0,%1,%2,%3}, [%4];" \
                 : "=r"(r0), "=r"(r1), "=r"(r2), "=r"(r3) : "r"(addr))

__device__ __forceinline__ void mma16816(float* d, const uint32_t* a, uint32_t b0, uint32_t b1) {
    asm volatile(
        "mma.sync.aligned.m16n8k16.row.col.f32.bf16.bf16.f32 "
        "{%0,%1,%2,%3}, {%4,%5,%6,%7}, {%8,%9}, {%0,%1,%2,%3};"
        : "+f"(d[0]), "+f"(d[1]), "+f"(d[2]), "+f"(d[3])
        : "r"(a[0]), "r"(a[1]), "r"(a[2]), "r"(a[3]), "r"(b0), "r"(b1));
}

// ---------------- device scratch ----------------
__device__ int            g_seg[L_SEQ * BATCH];
__device__ int            g_ustart[(NUTT + 1) * BATCH];
__device__ __nv_bfloat16  g_uhi[MTOT * EMB];
__device__ __nv_bfloat16  g_ulo[MTOT * EMB];
__device__ __nv_bfloat16  g_whi[2 * G4 * EMB];
__device__ __nv_bfloat16  g_wlo[2 * G4 * EMB];
__device__ float          g_xp[2ull * MTOT * G4];
__device__ float          g_h[2ull * MTOT * HID];
__device__ int            g_umask[MTOT];

__device__ __forceinline__ float sig_fast(float x) {
    return __fdividef(1.0f, 1.0f + __expf(-x));
}
__device__ __forceinline__ float tanh_fast(float x) {
    float t = __expf(2.0f * x);
    return 1.0f - __fdividef(2.0f, t + 1.0f);
}

// ---------------- K1: segment ids + utterance starts ----------------
__global__ void k1_seg(const int* __restrict__ x) {
    int b = blockIdx.x, tid = threadIdx.x;
    __shared__ int cnt[256];
    for (int i = tid; i <= NUTT; i += 256) g_ustart[i * BATCH + b] = L_SEQ;
    int base = tid * 8;
    int loc[8]; int c = 0;
    #pragma unroll
    for (int k = 0; k < 8; k++) {
        loc[k] = (x[(base + k) * BATCH + b] == SEP_TOK) ? 1 : 0;
        c += loc[k];
    }
    cnt[tid] = c;
    __syncthreads();
    for (int off = 1; off < 256; off <<= 1) {
        int v = (tid >= off) ? cnt[tid - off] : 0;
        __syncthreads();
        cnt[tid] += v;
        __syncthreads();
    }
    int run = (tid > 0) ? cnt[tid - 1] : 0;
    #pragma unroll
    for (int k = 0; k < 8; k++) {
        int t = base + k;
        g_seg[t * BATCH + b] = run;
        if (loc[k]) {
            if (run + 1 <= NUTT) g_ustart[(run + 1) * BATCH + b] = t + 1;
            run++;
        }
    }
    if (tid == 0) g_ustart[b] = 0;
}

// ---------------- K2: ragged mean-pool -> bf16 hi/lo ----------------
__global__ void k2_pool(const int* __restrict__ x, const float* __restrict__ emb) {
    int uu = blockIdx.x, b = blockIdx.y;
    __shared__ int rows[L_SEQ];
    __shared__ int se[2];
    if (threadIdx.x < 2)
        se[threadIdx.x] = g_ustart[(uu + threadIdx.x) * BATCH + b];
    __syncthreads();
    int s = se[0], e = se[1];
    for (int t = s + threadIdx.x; t < e; t += 256) rows[t - s] = x[t * BATCH + b];
    __syncthreads();
    int n = e - s;
    float sum = 0.f;
    for (int i = 0; i < n; i++)
        sum += emb[(size_t)rows[i] * EMB + threadIdx.x];
    float val = (n > 0) ? sum / (float)n : 0.f;
    size_t idx = ((size_t)uu * BATCH + b) * EMB + threadIdx.x;
    __nv_bfloat16 hi = __float2bfloat16(val);
    g_uhi[idx] = hi;
    g_ulo[idx] = __float2bfloat16(val - __bfloat162float(hi));
}

// ---------------- K3w: weight hi/lo conversion ----------------
__global__ void k3w_conv(const float* __restrict__ wihf, const float* __restrict__ wihb) {
    int n = blockIdx.x;
    int col = threadIdx.x;
    float w = (n < G4) ? wihf[(size_t)n * EMB + col] : wihb[(size_t)(n - G4) * EMB + col];
    __nv_bfloat16 hi = __float2bfloat16(w);
    size_t idx = (size_t)n * EMB + col;
    g_whi[idx] = hi;
    g_wlo[idx] = __float2bfloat16(w - __bfloat162float(hi));
}

// ---------------- K3b: HMMA GEMM xp = U @ Wcat^T + biases (unchanged, 57us) ----------------
#define K3_BM 128
#define K3_BN 64
#define K3_BK 64
#define K3_STR 72
#define K3_A_BYTES (K3_BM * K3_STR * 2)
#define K3_B_BYTES (K3_BN * K3_STR * 2)
#define K3_SMEM (2 * (K3_A_BYTES + K3_B_BYTES))

__global__ void __launch_bounds__(256) k3b_gemm(
    const float* __restrict__ bihf, const float* __restrict__ bhhf,
    const float* __restrict__ bihb, const float* __restrict__ bhhb) {
    extern __shared__ char dsm[];
    __shared__ float bias_sm[K3_BN];
    uint32_t smb = smem_to_u32(dsm);
    const uint32_t aoff[2] = {0u, (uint32_t)K3_A_BYTES};
    const uint32_t boff[2] = {(uint32_t)(2 * K3_A_BYTES), (uint32_t)(2 * K3_A_BYTES + K3_B_BYTES)};

    int tid = threadIdx.x;
    int wid = tid >> 5, lane = tid & 31;
    int warp_m = wid & 3, warp_n = wid >> 2;
    int m0 = blockIdx.x * K3_BM;
    int n0 = blockIdx.y * K3_BN;
    int dir = n0 >> 9;
    int gi0 = n0 & (G4 - 1);

    if (tid < K3_BN) {
        int gi = gi0 + tid;
        bias_sm[tid] = dir ? (bihb[gi] + bhhb[gi]) : (bihf[gi] + bhhf[gi]);
    }

    float acc[2][4][4];
    #pragma unroll
    for (int a = 0; a < 2; a++)
        #pragma unroll
        for (int b = 0; b < 4; b++)
            #pragma unroll
            for (int cc = 0; cc < 4; cc++) acc[a][b][cc] = 0.f;

    int arow = tid >> 3, ac8 = tid & 7;
    int brow = tid >> 3, bc8 = tid & 7;

    #define K3_LOAD_STAGE(ks, buf) do {                                              \
        int _s = (ks) >> 2;                                                          \
        int _k0 = ((ks) & 3) * K3_BK;                                                \
        const __nv_bfloat16* _As = (_s < 2) ? g_uhi : g_ulo;                         \
        const __nv_bfloat16* _Bs = (_s == 1) ? g_wlo : g_whi;                        \
        _Pragma("unroll")                                                            \
        for (int _i = 0; _i < 4; _i++) {                                             \
            int _r = arow + _i * 32;                                                 \
            const void* _g = _As + (size_t)(m0 + _r) * EMB + _k0 + ac8 * 8;          \
            uint32_t _d = smb + aoff[buf] + (uint32_t)(_r * K3_STR + ac8 * 8) * 2;   \
            CP_ASYNC16(_d, _g);                                                      \
        }                                                                            \
        _Pragma("unroll")                                                            \
        for (int _i = 0; _i < 2; _i++) {                                             \
            int _r = brow + _i * 32;                                                 \
            const void* _g = _Bs + (size_t)(n0 + _r) * EMB + _k0 + bc8 * 8;          \
            uint32_t _d = smb + boff[buf] + (uint32_t)(_r * K3_STR + bc8 * 8) * 2;   \
            CP_ASYNC16(_d, _g);                                                      \
        }                                                                            \
        CP_COMMIT();                                                                 \
    } while (0)

    K3_LOAD_STAGE(0, 0);

    #pragma unroll 1
    for (int ks = 0; ks < 12; ks++) {
        if (ks + 1 < 12) {
            K3_LOAD_STAGE(ks + 1, (ks + 1) & 1);
            CP_WAIT1();
        } else {
            CP_WAIT0();
        }
        __syncthreads();
        int buf = ks & 1;
        uint32_t Ab = smb + aoff[buf];
        uint32_t Bb = smb + boff[buf];
        #pragma unroll
        for (int kk = 0; kk < 4; kk++) {
            uint32_t af[2][4], bf[2][4];
            #pragma unroll
            for (int mt = 0; mt < 2; mt++) {
                int row = warp_m * 32 + mt * 16 + (lane & 15);
                int col = kk * 16 + (lane >> 4) * 8;
                LDMATRIX_X4(af[mt][0], af[mt][1], af[mt][2], af[mt][3],
                            Ab + (uint32_t)(row * K3_STR + col) * 2);
            }
            #pragma unroll
            for (int nt = 0; nt < 2; nt++) {
                int row = warp_n * 32 + nt * 16 + (lane & 15);
                int col = kk * 16 + (lane >> 4) * 8;
                LDMATRIX_X4(bf[nt][0], bf[nt][1], bf[nt][2], bf[nt][3],
                            Bb + (uint32_t)(row * K3_STR + col) * 2);
            }
            #pragma unroll
            for (int mt = 0; mt < 2; mt++)
                #pragma unroll
                for (int nt = 0; nt < 2; nt++) {
                    mma16816(acc[mt][nt * 2 + 0], af[mt], bf[nt][0], bf[nt][2]);
                    mma16816(acc[mt][nt * 2 + 1], af[mt], bf[nt][1], bf[nt][3]);
                }
        }
        __syncthreads();
    }

    int lrow = lane >> 2, lcol = (lane & 3) * 2;
    #pragma unroll
    for (int mt = 0; mt < 2; mt++) {
        int m = m0 + warp_m * 32 + mt * 16 + lrow;
        #pragma unroll
        for (int n8 = 0; n8 < 4; n8++) {
            int nl = warp_n * 32 + n8 * 8 + lcol;
            float b0 = bias_sm[nl], b1 = bias_sm[nl + 1];
            float2 v0 = make_float2(acc[mt][n8][0] + b0, acc[mt][n8][1] + b1);
            float2 v1 = make_float2(acc[mt][n8][2] + b0, acc[mt][n8][3] + b1);
            *(float2*)&g_xp[((size_t)dir * MTOT + m) * G4 + gi0 + nl]     = v0;
            *(float2*)&g_xp[((size_t)dir * MTOT + m + 8) * G4 + gi0 + nl] = v1;
        }
    }
}

// ---------------- K4: persistent BiLSTM (quad LDS + distributed activations) ----------------
// Thread tid owns gate rows: tid (i for tid<128, f else) and 256+tid (g / o).
// Weights: row A quads 0..15 (regs) + quads 16..31 (smem); row B full 32 quads (regs).
#define WQ_S   257                        // ulonglong2 stride
#define WQ_N   16                         // smem quads (row A, j=64..127)
#define K4_ACT (WQ_N * WQ_S)              // ulonglong2 index where act smem starts
#define K4_SMEM_BYTES (K4_ACT * 16 + (256 + 128) * 4)

__global__ void __launch_bounds__(256, 1) k4_lstm(
    const float* __restrict__ whhf, const float* __restrict__ whhb) {
    extern __shared__ ulonglong2 smq[];
    ulonglong2* ws4 = smq;
    float* act = (float*)(smq + K4_ACT);   // [0..127]=sig(f), [128..255]=sig(o)
    float* hsm = act + 256;                // 128 floats, 16B-aligned

    int bi = blockIdx.x;
    int dir = bi >> 6, b = bi & 63;
    const float* whh = dir ? whhb : whhf;
    int tid = threadIdx.x;
    bool lowhalf = (tid < 128);            // warp-uniform

    // smem weights: row A (tid) quads 16..31 (cols 64..127)
    #pragma unroll
    for (int q = 0; q < WQ_N; q++)
        ws4[q * WQ_S + tid] = *(const ulonglong2*)&whh[(size_t)tid * HID + 64 + 4 * q];
    // reg weights
    ulonglong2 wif4[16];
    {
        const ulonglong2* wr = (const ulonglong2*)(whh + (size_t)tid * HID);
        #pragma unroll
        for (int q = 0; q < 16; q++) wif4[q] = wr[q];
    }
    ulonglong2 wgo4[32];
    {
        const ulonglong2* wr = (const ulonglong2*)(whh + (size_t)(256 + tid) * HID);
        #pragma unroll
        for (int q = 0; q < 32; q++) wgo4[q] = wr[q];
    }
    if (tid < HID) hsm[tid] = 0.f;
    float c = 0.f;
    __syncthreads();

    int t0 = dir ? (NUTT - 1) : 0;
    size_t base0 = ((size_t)dir * MTOT + (size_t)t0 * BATCH + b) * G4;
    float xpA = g_xp[base0 + tid];
    float xpB = g_xp[base0 + 256 + tid];
    float xpA_n = 0.f, xpB_n = 0.f;

    #pragma unroll 1
    for (int s = 0; s < NUTT; s++) {
        int t = dir ? (NUTT - 1 - s) : s;
        if (s + 1 < NUTT) {
            int tn = dir ? (NUTT - 2 - s) : (s + 1);
            size_t bn = ((size_t)dir * MTOT + (size_t)tn * BATCH + b) * G4;
            xpA_n = g_xp[bn + tid];
            xpB_n = g_xp[bn + 256 + tid];
        }

        u64 aA0 = 0ull, aA1 = 0ull, aB0 = 0ull, aB1 = 0ull;
        // j = 0..63 : row A from regs
        #pragma unroll
        for (int u = 0; u < 16; u++) {
            ulonglong2 h2 = *(const ulonglong2*)&hsm[4 * u];
            aA0 = fma2(wif4[u].x, h2.x, aA0);
            aA1 = fma2(wif4[u].y, h2.y, aA1);
            aB0 = fma2(wgo4[u].x, h2.x, aB0);
            aB1 = fma2(wgo4[u].y, h2.y, aB1);
        }
        // j = 64..127 : row A from smem (quads), row B from regs
        #pragma unroll
        for (int u = 0; u < 16; u++) {
            ulonglong2 h2 = *(const ulonglong2*)&hsm[64 + 4 * u];
            ulonglong2 wq = ws4[u * WQ_S + tid];
            aA0 = fma2(wq.x, h2.x, aA0);
            aA1 = fma2(wq.y, h2.y, aA1);
            aB0 = fma2(wgo4[16 + u].x, h2.x, aB0);
            aB1 = fma2(wgo4[16 + u].y, h2.y, aB1);
        }
        float2 vA0 = unpack2(aA0), vA1 = unpack2(aA1);
        float2 vB0 = unpack2(aB0), vB1 = unpack2(aB1);
        float gA = (vA0.x + vA0.y) + (vA1.x + vA1.y) + xpA;   // i_j (lo) / f_j (hi)
        float gB = (vB0.x + vB0.y) + (vB1.x + vB1.y) + xpB;   // g_j (lo) / o_j (hi)

        // distributed activations (warp-uniform branch)
        float actA = sig_fast(gA);                              // sig(i) or sig(f)
        float actB = lowhalf ? tanh_fast(gB) : sig_fast(gB);    // tanh(g) or sig(o)
        if (!lowhalf) {
            act[tid - 128] = actA;      // sig(f_j) for unit j = tid-128
            act[tid]       = actB;      // sig(o_j) at [128 + j]
        }
        __syncthreads();
        if (lowhalf) {
            float sf = act[tid], so = act[128 + tid];
            c = sf * c + actA * actB;                 // sig(i)*tanh(g)
            float h = so * tanh_fast(c);
            hsm[tid] = h;
            g_h[(((size_t)dir * NUTT + t) * BATCH + b) * HID + tid] = h;
        }
        xpA = xpA_n;
        xpB = xpB_n;
        __syncthreads();
    }
}

// ---------------- K5: head (warp per (t,b)) ----------------
__global__ void k5_head(const float* __restrict__ wout, const float* __restrict__ bout,
                        float* __restrict__ out) {
    int w = threadIdx.x >> 5, lane = threadIdx.x & 31;
    int idx = blockIdx.x * 8 + w;
    if (idx >= MTOT) return;
    int t = idx >> 6, b = idx & 63;
    const float* hf = &g_h[(((size_t)0 * NUTT + t) * BATCH + b) * HID];
    const float* hb = &g_h[(((size_t)1 * NUTT + t) * BATCH + b) * HID];
    float l0 = 0.f, l1 = 0.f;
    #pragma unroll
    for (int q = 0; q < 4; q++) {
        int e = q * 32 + lane;
        float vf = hf[e], vb = hb[e];
        l0 += vf * wout[e] + vb * wout[HID + e];
        l1 += vf * wout[EMB + e] + vb * wout[EMB + HID + e];
    }
    #pragma unroll
    for (int off = 16; off > 0; off >>= 1) {
        l0 += __shfl_xor_sync(0xFFFFFFFFu, l0, off);
        l1 += __shfl_xor_sync(0xFFFFFFFFu, l1, off);
    }
    if (lane == 0) {
        l0 += bout[0]; l1 += bout[1];
        float m  = fmaxf(l0, l1);
        float e0 = expf(l0 - m), e1 = expf(l1 - m);
        float s  = e0 + e1;
        float p0 = e0 / s, p1 = e1 / s;
        int am = (l1 > l0) ? 1 : 0;
        out[idx * 2 + 0]         = l0;
        out[idx * 2 + 1]         = l1;
        out[16384 + idx * 2 + 0] = p0;
        out[16384 + idx * 2 + 1] = p1;
        out[32768 + idx]         = am ? p1 : p0;
        out[40960 + idx]         = (float)am;
        g_umask[idx]             = am;
    }
}

// ---------------- K6: expand mask to tokens ----------------
__global__ void k6_mask(const int* __restrict__ x, float* __restrict__ out) {
    int i = blockIdx.x * blockDim.x + threadIdx.x;
    if (i >= L_SEQ * BATCH) return;
    int b   = i & 63;
    int seg = g_seg[i];
    int m   = g_umask[seg * BATCH + b];
    out[49152 + i] = m ? (float)x[i] : 0.0f;
}

extern "C" void kernel_launch(void* const* d_in, const int* in_sizes, int n_in,
                              void* d_out, int out_size) {
    const int*   x    = (const int*)d_in[0];
    const float* emb  = (const float*)d_in[1];
    const float* wihf = (const float*)d_in[2];
    const float* whhf = (const float*)d_in[3];
    const float* bihf = (const float*)d_in[4];
    const float* bhhf = (const float*)d_in[5];
    const float* wihb = (const float*)d_in[6];
    const float* whhb = (const float*)d_in[7];
    const float* bihb = (const float*)d_in[8];
    const float* bhhb = (const float*)d_in[9];
    const float* wout = (const float*)d_in[10];
    const float* bout = (const float*)d_in[11];
    float* out = (float*)d_out;

    cudaFuncSetAttribute(k4_lstm, cudaFuncAttributeMaxDynamicSharedMemorySize, K4_SMEM_BYTES);
    cudaFuncSetAttribute(k3b_gemm, cudaFuncAttributeMaxDynamicSharedMemorySize, K3_SMEM);

    k3w_conv<<<2 * G4, EMB>>>(wihf, wihb);
    k1_seg <<<BATCH, 256>>>(x);
    k2_pool<<<dim3(NUTT, BATCH), 256>>>(x, emb);
    k3b_gemm<<<dim3(MTOT / K3_BM, (2 * G4) / K3_BN), 256, K3_SMEM>>>(bihf, bhhf, bihb, bhhb);
    k4_lstm<<<2 * BATCH, 256, K4_SMEM_BYTES>>>(whhf, whhb);
    k5_head<<<MTOT / 8, 256>>>(wout, bout, out);
    k6_mask<<<(L_SEQ * BATCH) / 256, 256>>>(x, out);
}